// round 6
// baseline (speedup 1.0000x reference)
#include <cuda_runtime.h>
#include <cstdint>

// B=4, P2=64, TOPK=16, W2=49, C_KV=512
// r_idx: int32 (B, P2, TOPK)    [JAX x64-off emits int32]
// kv:    float32 (B, P2, W2, C_KV)
// out:   float32 (B, P2, TOPK, W2, C_KV)
//
// Inverted gather: each kv source region is referenced by ~16 dest regions.
// Instead of 16 blocks each re-reading it from L2 (822MB total LTS traffic),
// build per-source destination lists, then read each source chunk ONCE and
// multicast-store it to all destinations (437MB LTS traffic).

#define B_    4
#define P2_   64
#define TOPK_ 16
#define W2_   49
#define CKV_  512

#define N_REGIONS   (B_ * P2_ * TOPK_)      // 4096 dest regions
#define N_SRC       (B_ * P2_)              // 256 source regions
#define REGION_F4   ((W2_ * CKV_) / 4)      // 6272 float4 per region
#define THREADS_    448
#define CHUNKS_     7                       // 7 chunks x 896 f4 (2 f4/thread)
#define CHUNK_F4    (REGION_F4 / CHUNKS_)   // 896
#define MAX_DEST    1024                    // worst case: all of one batch picks one r

// Scratch (device globals: allocation-guard-safe)
__device__ int g_cnt[N_SRC];
__device__ int g_list[N_SRC * MAX_DEST];

__global__ void zero_counts_kernel() {
    g_cnt[threadIdx.x] = 0;
}

__global__ void build_lists_kernel(const int* __restrict__ r_idx) {
    const int region = blockIdx.x * blockDim.x + threadIdx.x;   // 0..4095
    const int b = region >> 10;
    int r = __ldg(&r_idx[region]);
    r = min(max(r, 0), P2_ - 1);
    const int src = b * P2_ + r;
    const int slot = atomicAdd(&g_cnt[src], 1);
    g_list[src * MAX_DEST + slot] = region;
}

__global__ void __launch_bounds__(THREADS_, 4) gather_kernel(
    const float4* __restrict__ kv,
    float4*       __restrict__ out)
{
    const int src   = blockIdx.y;               // 0..255 = b*64 + r
    const int chunk = blockIdx.x;               // 0..6
    const int cnt   = g_cnt[src];
    if (cnt == 0) return;

    const int t = threadIdx.x;
    const long long src_off = (long long)src * REGION_F4 + chunk * CHUNK_F4;

    // Read this chunk ONCE (2 coalesced float4 per thread)
    const float4 v0 = __ldg(&kv[src_off + t]);
    const float4 v1 = __ldg(&kv[src_off + THREADS_ + t]);

    const int* __restrict__ list = &g_list[src * MAX_DEST];

    // Multicast to every destination region referencing this source
    for (int i = 0; i < cnt; i++) {
        const int region = __ldg(&list[i]);
        float4* __restrict__ dst = out + (long long)region * REGION_F4 + chunk * CHUNK_F4;
        __stcs(&dst[t], v0);
        __stcs(&dst[THREADS_ + t], v1);
    }
}

extern "C" void kernel_launch(void* const* d_in, const int* in_sizes, int n_in,
                              void* d_out, int out_size)
{
    const int*    r_idx = (const int*)d_in[0];
    const float4* kv    = (const float4*)d_in[1];
    float4*       out   = (float4*)d_out;

    zero_counts_kernel<<<1, N_SRC>>>();
    build_lists_kernel<<<N_REGIONS / 256, 256>>>(r_idx);

    dim3 grid(CHUNKS_, N_SRC);                  // (7, 256)
    gather_kernel<<<grid, THREADS_>>>(kv, out);
}

// round 7
// speedup vs baseline: 1.0503x; 1.0503x over previous
#include <cuda_runtime.h>
#include <cstdint>

// B=4, P2=64, TOPK=16, W2=49, C_KV=512
// r_idx: int32 (B, P2, TOPK)    [JAX x64-off emits int32]
// kv:    float32 (B, P2, W2, C_KV)
// out:   float32 (B, P2, TOPK, W2, C_KV)
//
// Fused inverted multicast gather:
//   block = (chunk 0..6, src 0..255).  Scan this batch's 1024 r_idx entries
//   (L2-resident, 4KB) into a shared-memory dest list, then read the 896-f4
//   source chunk ONCE and stream it to all cnt destinations.
//   LTS traffic: 26MB reads + 411MB writes (vs 822MB for the direct gather,
//   which sits exactly at the LTS throughput cap).

#define B_    4
#define P2_   64
#define TOPK_ 16
#define W2_   49
#define CKV_  512

#define N_REGIONS   (B_ * P2_ * TOPK_)      // 4096 dest regions
#define N_SRC       (B_ * P2_)              // 256 source regions
#define RPB_        (P2_ * TOPK_)           // 1024 regions per batch
#define REGION_F4   ((W2_ * CKV_) / 4)      // 6272 float4 per region
#define THREADS_    448
#define CHUNKS_     7
#define CHUNK_F4    (REGION_F4 / CHUNKS_)   // 896  (2 float4 per thread)

__global__ void __launch_bounds__(THREADS_, 3) kv_gather_kernel(
    const int*    __restrict__ r_idx,
    const float4* __restrict__ kv,
    float4*       __restrict__ out)
{
    __shared__ int s_cnt;
    __shared__ int s_list[RPB_];            // worst case: whole batch picks this r

    const int src   = blockIdx.y;           // 0..255 = b*64 + r
    const int chunk = blockIdx.x;           // 0..6
    const int b = src >> 6;
    const int r = src & 63;
    const int t = threadIdx.x;

    if (t == 0) s_cnt = 0;
    __syncthreads();

    // Scan this batch's r_idx (1024 ints, L2-resident) for matches.
    #pragma unroll
    for (int j = t; j < RPB_; j += THREADS_) {
        int ri = __ldg(&r_idx[b * RPB_ + j]);
        ri = min(max(ri, 0), P2_ - 1);
        if (ri == r) {
            int slot = atomicAdd(&s_cnt, 1);
            s_list[slot] = b * RPB_ + j;    // global dest region id
        }
    }
    __syncthreads();

    const int cnt = s_cnt;
    if (cnt == 0) return;

    // Read the source chunk ONCE: 2 coalesced float4 per thread.
    const long long src_off = (long long)src * REGION_F4 + chunk * CHUNK_F4;
    const float4 v0 = __ldg(&kv[src_off + t]);
    const float4 v1 = __ldg(&kv[src_off + THREADS_ + t]);

    const long long chunk_base = (long long)chunk * CHUNK_F4 + t;

    // Multicast to every destination region (list entries from SMEM, 29cyc).
    int next = s_list[0];
    for (int i = 0; i < cnt; i++) {
        const int region = next;
        if (i + 1 < cnt) next = s_list[i + 1];   // prefetch next list entry
        float4* __restrict__ dst = out + (long long)region * REGION_F4 + chunk_base;
        __stcs(&dst[0],        v0);
        __stcs(&dst[THREADS_], v1);
    }
}

extern "C" void kernel_launch(void* const* d_in, const int* in_sizes, int n_in,
                              void* d_out, int out_size)
{
    const int*    r_idx = (const int*)d_in[0];
    const float4* kv    = (const float4*)d_in[1];
    float4*       out   = (float4*)d_out;

    dim3 grid(CHUNKS_, N_SRC);              // (7, 256)
    kv_gather_kernel<<<grid, THREADS_>>>(r_idx, kv, out);
}